// round 8
// baseline (speedup 1.0000x reference)
#include <cuda_runtime.h>
#include <cuda_fp16.h>
#include <cstdint>

// ============================================================================
// BinaryDense: y[M,N] = x[M,K] @ binarize(w)[K,N] + bias,  M=2^21, K=N=128
//
// NOTE: this toolchain assembles PTX at target sm_103 (no 'a' suffix), so
// tcgen05/TMEM are unavailable. Tensor cores are used via the baseline
// mma.sync.m16n8k16 (HMMA) + ldmatrix path instead.
//
// R7 diagnosis: rel_err 0.5903 == exact prediction for "stochastic bernoulli
// bits uncorrelated with JAX" => GEMM correct, RNG layout wrong. JAX >=0.4.30
// defaults to jax_threefry_partitionable=True: bits[i] = f(key, i) elementwise
// with counter pair (hi = i>>32 = 0, lo = i) and 32-bit output = out0 ^ out1.
// This round switches the prologue to that layout (only change).
// ============================================================================

#define SMEM_BIAS     16                  // 512 B
#define SMEM_A_HI     1024
#define SMEM_A_LO     (1024 + 32768)
#define SMEM_B        (1024 + 65536)
#define SMEM_TOTAL    (1024 + 3 * 32768)  // 99328 B -> 2 CTAs/SM

#define TILE_ELEMS    (128 * 128)

// ---------------------------------------------------------------------------
// PTX helpers (baseline ISA only — no sm_103a features)
// ---------------------------------------------------------------------------
__device__ __forceinline__ uint32_t smem_u32(const void* p) {
    uint32_t a;
    asm("{ .reg .u64 t; cvta.to.shared.u64 t, %1; cvt.u32.u64 %0, t; }"
        : "=r"(a) : "l"(p));
    return a;
}

#define LDMATRIX_X4(r0, r1, r2, r3, addr) \
    asm volatile("ldmatrix.sync.aligned.m8n8.x4.shared.b16 {%0,%1,%2,%3}, [%4];" \
        : "=r"(r0), "=r"(r1), "=r"(r2), "=r"(r3) : "r"(addr))

#define MMA16816(c0, c1, c2, c3, a0, a1, a2, a3, b0, b1) \
    asm volatile("mma.sync.aligned.m16n8k16.row.col.f32.f16.f16.f32 " \
        "{%0,%1,%2,%3}, {%4,%5,%6,%7}, {%8,%9}, {%0,%1,%2,%3};" \
        : "+f"(c0), "+f"(c1), "+f"(c2), "+f"(c3) \
        : "r"(a0), "r"(a1), "r"(a2), "r"(a3), "r"(b0), "r"(b1))

// Swizzled offset within a 128x128 fp16 tile stored with 256B logical rows.
// 16B chunk index XOR row&15 -> every ldmatrix 8-address phase hits 8
// distinct 16B offsets mod 128B => conflict-free LDS.
__device__ __host__ __forceinline__ uint32_t tile_off_sw(int row, int col) {
    return (uint32_t)row * 256u
         + ((uint32_t)(((col >> 3) ^ (row & 15)) & 31) << 4)
         + ((uint32_t)(col & 7) << 1);
}

// ---------------------------------------------------------------------------
// Prologue: bit-exact JAX (partitionable) threefry2x32 binarization of w into
// the swizzled image of B = w_bin^T ([N][K] fp16, +1/-1).
// ---------------------------------------------------------------------------
__device__ __align__(16) unsigned char g_Bimg[32768];

__device__ __forceinline__ uint32_t rotl32(uint32_t x, int r) {
    return (x << r) | (x >> (32 - r));
}

__device__ __forceinline__ void threefry2x32_k42(uint32_t c0, uint32_t c1,
                                                 uint32_t& o0, uint32_t& o1) {
    const uint32_t ks0 = 0u, ks1 = 42u, ks2 = 0x1BD11BDAu ^ 0u ^ 42u;
    uint32_t x0 = c0 + ks0, x1 = c1 + ks1;
#define TF_R(r) { x0 += x1; x1 = rotl32(x1, r); x1 ^= x0; }
    TF_R(13) TF_R(15) TF_R(26) TF_R(6)  x0 += ks1; x1 += ks2 + 1u;
    TF_R(17) TF_R(29) TF_R(16) TF_R(24) x0 += ks2; x1 += ks0 + 2u;
    TF_R(13) TF_R(15) TF_R(26) TF_R(6)  x0 += ks0; x1 += ks1 + 3u;
    TF_R(17) TF_R(29) TF_R(16) TF_R(24) x0 += ks1; x1 += ks2 + 4u;
    TF_R(13) TF_R(15) TF_R(26) TF_R(6)  x0 += ks2; x1 += ks0 + 5u;
#undef TF_R
    o0 = x0; o1 = x1;
}

__global__ void binarize_kernel(const float* __restrict__ w) {
    // Partitionable threefry layout: element i (linear, row-major over (K,N))
    // uses counter pair (hi = i>>32 = 0, lo = i); 32-bit bits = out0 ^ out1.
    int i = blockIdx.x * blockDim.x + threadIdx.x;
    if (i < 16384) {
        uint32_t o0, o1;
        threefry2x32_k42(0u, (uint32_t)i, o0, o1);
        uint32_t bits = o0 ^ o1;
        // u = uniform [0,1) exactly as jax.random.uniform(float32):
        // bitcast((bits >> 9) | 0x3f800000) - 1.0
        float u = __uint_as_float((bits >> 9) | 0x3F800000u) - 1.0f;
        float p = fminf(fmaxf((w[i] + 1.0f) * 0.5f, 0.0f), 1.0f);
        int k = i >> 7;      // weight row (K index)
        int n = i & 127;     // weight col (N index)
        uint16_t v = (u < p) ? (uint16_t)0x3C00 : (uint16_t)0xBC00;  // +1/-1 fp16
        *(uint16_t*)(g_Bimg + tile_off_sw(n, k)) = v;  // B[n][k] = w_bin[k][n]
    }
}

// ---------------------------------------------------------------------------
// Persistent GEMM kernel: 8 warps/CTA, each warp owns 16 rows x 128 cols.
// ---------------------------------------------------------------------------
__global__ __launch_bounds__(256, 2)
void bdense_kernel(const float* __restrict__ x,
                   const float* __restrict__ bias,
                   float* __restrict__ out,
                   int num_tiles) {
    extern __shared__ __align__(1024) char smem[];
    uint32_t smem_base = smem_u32(smem);
    int tid = threadIdx.x;
    int wid = tid >> 5;
    int lane = tid & 31;

    // One-time setup: B image (already swizzled) + bias to SMEM.
    {
        const uint4* src = (const uint4*)g_Bimg;
        uint4* dst = (uint4*)(smem + SMEM_B);
        for (int i = tid; i < 2048; i += 256) dst[i] = src[i];
        if (tid < 128) ((float*)(smem + SMEM_BIAS))[tid] = bias[tid];
    }
    __syncthreads();

    const float* sbias = (const float*)(smem + SMEM_BIAS);

    // Lane-invariant ldmatrix address components.
    int quad = lane >> 3, lr = lane & 7;
    // A x4: matrices 0..3 = a0..a3: rows (quad&1)*8+lr, k-chunk base (quad>>1)
    int arow = wid * 16 + (quad & 1) * 8 + lr;
    int akc  = quad >> 1;
    // B x4: matrices (n-lo,k-lo),(n-lo,k-hi),(n-hi,k-lo),(n-hi,k-hi):
    //       n-rows (quad>>1)*8+lr, k-chunk (quad&1)
    int bnrow_off = (quad >> 1) * 8 + lr;
    int bkc  = quad & 1;

    for (int t = blockIdx.x; t < num_tiles; t += gridDim.x) {
        // ---- Load x tile (128x128 fp32), split hi/lo fp16, STS swizzled.
        //      unroll 4: 2 CTAs x 256 thr x 4 x 16B = 32KB in flight/SM
        //      (above ~18KB Little's-law need) without register spills. ----
        {
            const float4* xg = (const float4*)(x + (size_t)t * TILE_ELEMS);
#pragma unroll 4
            for (int i = tid; i < TILE_ELEMS / 4; i += 256) {
                float4 v = xg[i];
                int idx = i << 2;
                int row = idx >> 7;
                int col = idx & 127;
                __half2 h01 = __floats2half2_rn(v.x, v.y);
                __half2 h23 = __floats2half2_rn(v.z, v.w);
                float lx = v.x - __half2float(__low2half(h01));
                float ly = v.y - __half2float(__high2half(h01));
                float lz = v.z - __half2float(__low2half(h23));
                float lw = v.w - __half2float(__high2half(h23));
                __half2 l01 = __floats2half2_rn(lx, ly);
                __half2 l23 = __floats2half2_rn(lz, lw);
                union { __half2 h; uint32_t u; } p0, p1, q0, q1;
                p0.h = h01; p1.h = h23; q0.h = l01; q1.h = l23;
                // col%4==0 -> 4 fp16 stay inside one 16B swizzle chunk, 8B aligned
                uint32_t sw = tile_off_sw(row, col);
                *(uint2*)(smem + SMEM_A_HI + sw) = make_uint2(p0.u, p1.u);
                *(uint2*)(smem + SMEM_A_LO + sw) = make_uint2(q0.u, q1.u);
            }
        }
        __syncthreads();

        // ---- HMMA mainloop: 8 k-steps x 8 n-pairs x (hi+lo) = 256 mma/warp ----
        float acc[16][4];
#pragma unroll
        for (int ns = 0; ns < 16; ns++)
#pragma unroll
            for (int j = 0; j < 4; j++) acc[ns][j] = 0.0f;

#pragma unroll
        for (int ks = 0; ks < 8; ks++) {
            uint32_t a_off = (uint32_t)arow * 256u
                           + ((uint32_t)((((ks << 1) | akc) ^ (arow & 15)) & 31) << 4);
            uint32_t ah0, ah1, ah2, ah3, al0, al1, al2, al3;
            LDMATRIX_X4(ah0, ah1, ah2, ah3, smem_base + SMEM_A_HI + a_off);
            LDMATRIX_X4(al0, al1, al2, al3, smem_base + SMEM_A_LO + a_off);
#pragma unroll
            for (int ns2 = 0; ns2 < 8; ns2++) {
                int nrow = ns2 * 16 + bnrow_off;
                uint32_t b_off = (uint32_t)nrow * 256u
                               + ((uint32_t)((((ks << 1) | bkc) ^ (nrow & 15)) & 31) << 4);
                uint32_t b0, b1, b2, b3;
                LDMATRIX_X4(b0, b1, b2, b3, smem_base + SMEM_B + b_off);
                MMA16816(acc[2*ns2][0], acc[2*ns2][1], acc[2*ns2][2], acc[2*ns2][3],
                         ah0, ah1, ah2, ah3, b0, b1);
                MMA16816(acc[2*ns2+1][0], acc[2*ns2+1][1], acc[2*ns2+1][2], acc[2*ns2+1][3],
                         ah0, ah1, ah2, ah3, b2, b3);
                MMA16816(acc[2*ns2][0], acc[2*ns2][1], acc[2*ns2][2], acc[2*ns2][3],
                         al0, al1, al2, al3, b0, b1);
                MMA16816(acc[2*ns2+1][0], acc[2*ns2+1][1], acc[2*ns2+1][2], acc[2*ns2+1][3],
                         al0, al1, al2, al3, b2, b3);
            }
        }

        // A-SMEM read phase is over; barrier BEFORE the epilogue so no warp's
        // store tail gates other warps' next-tile LDGs (epilogue touches only
        // registers + GMEM, never A-SMEM).
        __syncthreads();

        // ---- Epilogue: +bias, streaming 8B stores (rows g and g+8) ----
        {
            int g = lane >> 2, tg = lane & 3;
            size_t r0 = (size_t)t * 128 + wid * 16 + g;
            float* orow0 = out + r0 * 128;
            float* orow1 = orow0 + 8 * 128;
#pragma unroll
            for (int ns = 0; ns < 16; ns++) {
                int cb = ns * 8 + 2 * tg;
                float2 bb = *(const float2*)(sbias + cb);
                float v0 = acc[ns][0] + bb.x;
                float v1 = acc[ns][1] + bb.y;
                float v2 = acc[ns][2] + bb.x;
                float v3 = acc[ns][3] + bb.y;
                asm volatile("st.global.cs.v2.f32 [%0], {%1, %2};"
                             :: "l"(orow0 + cb), "f"(v0), "f"(v1) : "memory");
                asm volatile("st.global.cs.v2.f32 [%0], {%1, %2};"
                             :: "l"(orow1 + cb), "f"(v2), "f"(v3) : "memory");
            }
        }
    }
}

// ---------------------------------------------------------------------------
// Harness entry point
// ---------------------------------------------------------------------------
extern "C" void kernel_launch(void* const* d_in, const int* in_sizes, int n_in,
                              void* d_out, int out_size) {
    const float* x    = (const float*)d_in[0];
    const float* w    = (const float*)d_in[1];
    const float* bias = (const float*)d_in[2];
    float* out = (float*)d_out;

    int num_tiles = (in_sizes[0] / 128) / 128;   // M / 128

    int sms = 0;
    if (cudaDeviceGetAttribute(&sms, cudaDevAttrMultiProcessorCount, 0)
            != cudaSuccess || sms <= 0)
        sms = 148;
    int grid = 2 * sms;
    if (grid > num_tiles) grid = num_tiles;
    if (grid < 1) grid = 1;

    cudaFuncSetAttribute(bdense_kernel,
                         cudaFuncAttributeMaxDynamicSharedMemorySize, SMEM_TOTAL);

    binarize_kernel<<<64, 256>>>(w);
    bdense_kernel<<<grid, 256, SMEM_TOTAL>>>(x, bias, out, num_tiles);
}

// round 9
// speedup vs baseline: 1.1561x; 1.1561x over previous
#include <cuda_runtime.h>
#include <cuda_fp16.h>
#include <cstdint>

// ============================================================================
// BinaryDense: y[M,N] = x[M,K] @ binarize(w)[K,N] + bias,  M=2^21, K=N=128
//
// R8 post-mortem: PASSED at 571us, rel_err 3.1e-7 (hi+lo fp16 split).
//   DRAM 46.5%, tensor 39.8%, occ 24.3% -> latency/serialization-bound,
//   traffic already minimal (2.1GB). rel_err margin is 3000x => drop the lo
//   pass: 1/2 tensor work, 1/2 cvt+STS, -32KB SMEM -> 3 CTAs/SM (occ 36%).
//   Expected fp16-RN-only error ~1.5e-4 (6x under threshold).
//
// Persistent-CTA fp16 HMMA GEMM (mma.sync.m16n8k16 + ldmatrix; tcgen05 is
// unavailable because ptxas here targets sm_103 base, not sm_103a).
// ============================================================================

#define SMEM_BIAS     16                  // 512 B
#define SMEM_A        1024
#define SMEM_B        (1024 + 32768)
#define SMEM_TOTAL    (1024 + 2 * 32768)  // 66560 B -> 3 CTAs/SM

#define TILE_ELEMS    (128 * 128)

// ---------------------------------------------------------------------------
// PTX helpers (baseline ISA only — no sm_103a features)
// ---------------------------------------------------------------------------
__device__ __forceinline__ uint32_t smem_u32(const void* p) {
    uint32_t a;
    asm("{ .reg .u64 t; cvta.to.shared.u64 t, %1; cvt.u32.u64 %0, t; }"
        : "=r"(a) : "l"(p));
    return a;
}

#define LDMATRIX_X4(r0, r1, r2, r3, addr) \
    asm volatile("ldmatrix.sync.aligned.m8n8.x4.shared.b16 {%0,%1,%2,%3}, [%4];" \
        : "=r"(r0), "=r"(r1), "=r"(r2), "=r"(r3) : "r"(addr))

#define MMA16816(c0, c1, c2, c3, a0, a1, a2, a3, b0, b1) \
    asm volatile("mma.sync.aligned.m16n8k16.row.col.f32.f16.f16.f32 " \
        "{%0,%1,%2,%3}, {%4,%5,%6,%7}, {%8,%9}, {%0,%1,%2,%3};" \
        : "+f"(c0), "+f"(c1), "+f"(c2), "+f"(c3) \
        : "r"(a0), "r"(a1), "r"(a2), "r"(a3), "r"(b0), "r"(b1))

// Swizzled offset within a 128x128 fp16 tile stored with 256B logical rows.
// 16B chunk index XOR row&15 -> every ldmatrix 8-address phase hits 8
// distinct 16B offsets mod 128B => conflict-free LDS.
__device__ __host__ __forceinline__ uint32_t tile_off_sw(int row, int col) {
    return (uint32_t)row * 256u
         + ((uint32_t)(((col >> 3) ^ (row & 15)) & 31) << 4)
         + ((uint32_t)(col & 7) << 1);
}

// ---------------------------------------------------------------------------
// Prologue: bit-exact JAX (partitionable) threefry2x32 binarization of w into
// the swizzled image of B = w_bin^T ([N][K] fp16, +1/-1).  (Verified R8.)
// ---------------------------------------------------------------------------
__device__ __align__(16) unsigned char g_Bimg[32768];

__device__ __forceinline__ uint32_t rotl32(uint32_t x, int r) {
    return (x << r) | (x >> (32 - r));
}

__device__ __forceinline__ void threefry2x32_k42(uint32_t c0, uint32_t c1,
                                                 uint32_t& o0, uint32_t& o1) {
    const uint32_t ks0 = 0u, ks1 = 42u, ks2 = 0x1BD11BDAu ^ 0u ^ 42u;
    uint32_t x0 = c0 + ks0, x1 = c1 + ks1;
#define TF_R(r) { x0 += x1; x1 = rotl32(x1, r); x1 ^= x0; }
    TF_R(13) TF_R(15) TF_R(26) TF_R(6)  x0 += ks1; x1 += ks2 + 1u;
    TF_R(17) TF_R(29) TF_R(16) TF_R(24) x0 += ks2; x1 += ks0 + 2u;
    TF_R(13) TF_R(15) TF_R(26) TF_R(6)  x0 += ks0; x1 += ks1 + 3u;
    TF_R(17) TF_R(29) TF_R(16) TF_R(24) x0 += ks1; x1 += ks2 + 4u;
    TF_R(13) TF_R(15) TF_R(26) TF_R(6)  x0 += ks2; x1 += ks0 + 5u;
#undef TF_R
    o0 = x0; o1 = x1;
}

__global__ void binarize_kernel(const float* __restrict__ w) {
    // Partitionable threefry layout: element i (linear, row-major over (K,N))
    // uses counter pair (hi = i>>32 = 0, lo = i); 32-bit bits = out0 ^ out1.
    int i = blockIdx.x * blockDim.x + threadIdx.x;
    if (i < 16384) {
        uint32_t o0, o1;
        threefry2x32_k42(0u, (uint32_t)i, o0, o1);
        uint32_t bits = o0 ^ o1;
        // u = uniform [0,1) exactly as jax.random.uniform(float32):
        // bitcast((bits >> 9) | 0x3f800000) - 1.0
        float u = __uint_as_float((bits >> 9) | 0x3F800000u) - 1.0f;
        float p = fminf(fmaxf((w[i] + 1.0f) * 0.5f, 0.0f), 1.0f);
        int k = i >> 7;      // weight row (K index)
        int n = i & 127;     // weight col (N index)
        uint16_t v = (u < p) ? (uint16_t)0x3C00 : (uint16_t)0xBC00;  // +1/-1 fp16
        *(uint16_t*)(g_Bimg + tile_off_sw(n, k)) = v;  // B[n][k] = w_bin[k][n]
    }
}

// ---------------------------------------------------------------------------
// Persistent GEMM kernel: 8 warps/CTA, each warp owns 16 rows x 128 cols.
// 3 CTAs/SM (66KB SMEM, <=84 regs target).
// ---------------------------------------------------------------------------
__global__ __launch_bounds__(256, 3)
void bdense_kernel(const float* __restrict__ x,
                   const float* __restrict__ bias,
                   float* __restrict__ out,
                   int num_tiles) {
    extern __shared__ __align__(1024) char smem[];
    uint32_t smem_base = smem_u32(smem);
    int tid = threadIdx.x;
    int wid = tid >> 5;
    int lane = tid & 31;

    // One-time setup: B image (already swizzled) + bias to SMEM.
    {
        const uint4* src = (const uint4*)g_Bimg;
        uint4* dst = (uint4*)(smem + SMEM_B);
        for (int i = tid; i < 2048; i += 256) dst[i] = src[i];
        if (tid < 128) ((float*)(smem + SMEM_BIAS))[tid] = bias[tid];
    }
    __syncthreads();

    const float* sbias = (const float*)(smem + SMEM_BIAS);

    // Lane-invariant ldmatrix address components.
    int quad = lane >> 3, lr = lane & 7;
    // A x4: matrices 0..3 = a0..a3: rows (quad&1)*8+lr, k-chunk base (quad>>1)
    int arow = wid * 16 + (quad & 1) * 8 + lr;
    int akc  = quad >> 1;
    // B x4: matrices (n-lo,k-lo),(n-lo,k-hi),(n-hi,k-lo),(n-hi,k-hi):
    //       n-rows (quad>>1)*8+lr, k-chunk (quad&1)
    int bnrow_off = (quad >> 1) * 8 + lr;
    int bkc  = quad & 1;

    for (int t = blockIdx.x; t < num_tiles; t += gridDim.x) {
        // ---- Load x tile (128x128 fp32), cvt fp16, STS swizzled.
        //      3 CTAs x 256 thr x 4 x 16B = 48KB in flight/SM (Little's law
        //      needs ~18KB for full DRAM BW). ----
        {
            const float4* xg = (const float4*)(x + (size_t)t * TILE_ELEMS);
#pragma unroll 4
            for (int i = tid; i < TILE_ELEMS / 4; i += 256) {
                float4 v = xg[i];
                int idx = i << 2;
                int row = idx >> 7;
                int col = idx & 127;
                union { __half2 h; uint32_t u; } p0, p1;
                p0.h = __floats2half2_rn(v.x, v.y);
                p1.h = __floats2half2_rn(v.z, v.w);
                // col%4==0 -> 4 fp16 stay inside one 16B swizzle chunk, 8B aligned
                uint32_t sw = tile_off_sw(row, col);
                *(uint2*)(smem + SMEM_A + sw) = make_uint2(p0.u, p1.u);
            }
        }
        __syncthreads();

        // ---- HMMA mainloop: 8 k-steps x 8 n-pairs = 128 mma/warp ----
        float acc[16][4];
#pragma unroll
        for (int ns = 0; ns < 16; ns++)
#pragma unroll
            for (int j = 0; j < 4; j++) acc[ns][j] = 0.0f;

#pragma unroll
        for (int ks = 0; ks < 8; ks++) {
            uint32_t a_off = (uint32_t)arow * 256u
                           + ((uint32_t)((((ks << 1) | akc) ^ (arow & 15)) & 31) << 4);
            uint32_t ah0, ah1, ah2, ah3;
            LDMATRIX_X4(ah0, ah1, ah2, ah3, smem_base + SMEM_A + a_off);
#pragma unroll
            for (int ns2 = 0; ns2 < 8; ns2++) {
                int nrow = ns2 * 16 + bnrow_off;
                uint32_t b_off = (uint32_t)nrow * 256u
                               + ((uint32_t)((((ks << 1) | bkc) ^ (nrow & 15)) & 31) << 4);
                uint32_t b0, b1, b2, b3;
                LDMATRIX_X4(b0, b1, b2, b3, smem_base + SMEM_B + b_off);
                MMA16816(acc[2*ns2][0], acc[2*ns2][1], acc[2*ns2][2], acc[2*ns2][3],
                         ah0, ah1, ah2, ah3, b0, b1);
                MMA16816(acc[2*ns2+1][0], acc[2*ns2+1][1], acc[2*ns2+1][2], acc[2*ns2+1][3],
                         ah0, ah1, ah2, ah3, b2, b3);
            }
        }

        // A-SMEM read phase is over; barrier BEFORE the epilogue so no warp's
        // store tail gates other warps' next-tile LDGs (epilogue touches only
        // registers + GMEM, never A-SMEM).
        __syncthreads();

        // ---- Epilogue: +bias, streaming 8B stores (rows g and g+8) ----
        {
            int g = lane >> 2, tg = lane & 3;
            size_t r0 = (size_t)t * 128 + wid * 16 + g;
            float* orow0 = out + r0 * 128;
            float* orow1 = orow0 + 8 * 128;
#pragma unroll
            for (int ns = 0; ns < 16; ns++) {
                int cb = ns * 8 + 2 * tg;
                float2 bb = *(const float2*)(sbias + cb);
                float v0 = acc[ns][0] + bb.x;
                float v1 = acc[ns][1] + bb.y;
                float v2 = acc[ns][2] + bb.x;
                float v3 = acc[ns][3] + bb.y;
                asm volatile("st.global.cs.v2.f32 [%0], {%1, %2};"
                             :: "l"(orow0 + cb), "f"(v0), "f"(v1) : "memory");
                asm volatile("st.global.cs.v2.f32 [%0], {%1, %2};"
                             :: "l"(orow1 + cb), "f"(v2), "f"(v3) : "memory");
            }
        }
    }
}

// ---------------------------------------------------------------------------
// Harness entry point
// ---------------------------------------------------------------------------
extern "C" void kernel_launch(void* const* d_in, const int* in_sizes, int n_in,
                              void* d_out, int out_size) {
    const float* x    = (const float*)d_in[0];
    const float* w    = (const float*)d_in[1];
    const float* bias = (const float*)d_in[2];
    float* out = (float*)d_out;

    int num_tiles = (in_sizes[0] / 128) / 128;   // M / 128

    int sms = 0;
    if (cudaDeviceGetAttribute(&sms, cudaDevAttrMultiProcessorCount, 0)
            != cudaSuccess || sms <= 0)
        sms = 148;
    int grid = 3 * sms;
    if (grid > num_tiles) grid = num_tiles;
    if (grid < 1) grid = 1;

    cudaFuncSetAttribute(bdense_kernel,
                         cudaFuncAttributeMaxDynamicSharedMemorySize, SMEM_TOTAL);

    binarize_kernel<<<64, 256>>>(w);
    bdense_kernel<<<grid, 256, SMEM_TOTAL>>>(x, bias, out, num_tiles);
}